// round 1
// baseline (speedup 1.0000x reference)
#include <cuda_runtime.h>
#include <math.h>

#define S    4096
#define DM   768
#define DF   3072
#define NE   8
#define TOPK 2
#define BM   64
#define BN   64
#define BK   16
#define MTILES  136                 // 136*64 = 8704 >= 8192 + 8*63 padded rows
#define MAXROWS (MTILES * BM)

// ---------------- device scratch (static: no allocs allowed) ----------------
__device__ int   g_topi[TOPK * S];
__device__ float g_topw[TOPK * S];
__device__ int   g_counts[NE];
__device__ int   g_fill[NE];
__device__ int   g_padoff[NE + 1];
__device__ int   g_row_token[MAXROWS];
__device__ int   g_row_expert[MAXROWS];
__device__ float g_row_w[MAXROWS];
__device__ __align__(16) float g_h[(size_t)MAXROWS * DF];   // ~107 MB scratch

// ---------------- init: zero output + reset tables ----------------
__global__ void init_kernel(float* __restrict__ out, int out_n) {
    int i = blockIdx.x * blockDim.x + threadIdx.x;
    if (i < out_n) out[i] = 0.0f;
    if (i < MAXROWS) { g_row_token[i] = -1; g_row_w[i] = 0.0f; }
    if (i < NE) { g_counts[i] = 0; g_fill[i] = 0; }
}

// ---------------- routing: logits -> top-2 -> renormalized weights ----------------
__global__ __launch_bounds__(128) void route_kernel(const float* __restrict__ x,
                                                    const float* __restrict__ Wg) {
    const int s = blockIdx.x;
    const float* __restrict__ xr = x + (size_t)s * DM;
    float acc[NE];
#pragma unroll
    for (int e = 0; e < NE; e++) acc[e] = 0.0f;

    for (int kk = threadIdx.x; kk < DM; kk += 128) {
        float xv = xr[kk];
#pragma unroll
        for (int e = 0; e < NE; e++) acc[e] = fmaf(xv, Wg[kk * NE + e], acc[e]);
    }
    // warp reduce
#pragma unroll
    for (int e = 0; e < NE; e++)
#pragma unroll
        for (int o = 16; o > 0; o >>= 1) acc[e] += __shfl_xor_sync(0xFFFFFFFFu, acc[e], o);

    __shared__ float sred[4][NE];
    int warp = threadIdx.x >> 5, lane = threadIdx.x & 31;
    if (lane == 0) {
#pragma unroll
        for (int e = 0; e < NE; e++) sred[warp][e] = acc[e];
    }
    __syncthreads();

    if (threadIdx.x == 0) {
        float l[NE];
#pragma unroll
        for (int e = 0; e < NE; e++)
            l[e] = sred[0][e] + sred[1][e] + sred[2][e] + sred[3][e];

        int i1 = 0;
#pragma unroll
        for (int e = 1; e < NE; e++) if (l[e] > l[i1]) i1 = e;
        int i2 = (i1 == 0) ? 1 : 0;
#pragma unroll
        for (int e = 0; e < NE; e++) if (e != i1 && l[e] > l[i2]) i2 = e;

        float d  = __expf(l[i2] - l[i1]);   // <= 1
        float inv = 1.0f / (1.0f + d);
        float w1 = inv;
        float w2 = d * inv;

        g_topi[0 * S + s] = i1; g_topw[0 * S + s] = w1;
        g_topi[1 * S + s] = i2; g_topw[1 * S + s] = w2;
        atomicAdd(&g_counts[i1], 1);
        atomicAdd(&g_counts[i2], 1);
    }
}

// ---------------- scan: padded offsets + per-row expert id ----------------
__global__ void scan_kernel() {
    __shared__ int off[NE + 1];
    if (threadIdx.x == 0) {
        int acc = 0;
        for (int e = 0; e < NE; e++) {
            off[e] = acc;
            g_padoff[e] = acc;
            acc += ((g_counts[e] + BM - 1) / BM) * BM;
        }
        off[NE] = acc;
        g_padoff[NE] = acc;
    }
    __syncthreads();
    for (int r = threadIdx.x; r < MAXROWS; r += blockDim.x) {
        int e = 0;
#pragma unroll
        for (int j = 1; j < NE; j++) if (r >= off[j]) e = j;
        g_row_expert[r] = (r < off[NE]) ? e : 0;
    }
}

// ---------------- fill: scatter slots into expert-sorted padded rows ----------------
__global__ void fill_kernel() {
    int i = blockIdx.x * blockDim.x + threadIdx.x;   // slot = k*S + s
    if (i >= S * TOPK) return;
    int e = g_topi[i];
    int pos = atomicAdd(&g_fill[e], 1);
    int row = g_padoff[e] + pos;
    g_row_token[row] = i & (S - 1);   // S = 4096 power of two
    g_row_w[row] = g_topw[i];
}

// ---------------- GEMM1: h = relu(X_gather @ W1[e] + b1[e]) ----------------
__global__ __launch_bounds__(256) void gemm1_kernel(const float* __restrict__ x,
                                                    const float* __restrict__ W1,
                                                    const float* __restrict__ b1) {
    __shared__ float As[BK][BM];
    __shared__ float Bs[BK][BN];
    const int n0 = blockIdx.x * BN;
    const int m0 = blockIdx.y * BM;
    const int e  = g_row_expert[m0];
    const float* __restrict__ W = W1 + (size_t)e * DM * DF;

    const int tid = threadIdx.x;
    const int am = tid >> 2, ak = (tid & 3) << 2;      // A: 64 rows x 16 k, float4
    const int bk = tid >> 4, bn = (tid & 15) << 2;     // B: 16 k x 64 n, float4
    const int tx = tid & 15, ty = tid >> 4;

    const int tok = g_row_token[m0 + am];
    const bool valid = (tok >= 0);
    const float* __restrict__ xrow = x + (size_t)(valid ? tok : 0) * DM;

    float acc[4][4];
#pragma unroll
    for (int i = 0; i < 4; i++)
#pragma unroll
        for (int j = 0; j < 4; j++) acc[i][j] = 0.0f;

    for (int k0 = 0; k0 < DM; k0 += BK) {
        float4 av = valid ? *(const float4*)(xrow + k0 + ak)
                          : make_float4(0.f, 0.f, 0.f, 0.f);
        As[ak + 0][am] = av.x; As[ak + 1][am] = av.y;
        As[ak + 2][am] = av.z; As[ak + 3][am] = av.w;
        *(float4*)&Bs[bk][bn] = *(const float4*)(W + (size_t)(k0 + bk) * DF + n0 + bn);
        __syncthreads();
#pragma unroll
        for (int kk = 0; kk < BK; kk++) {
            float a[4], b[4];
#pragma unroll
            for (int i = 0; i < 4; i++) a[i] = As[kk][(ty << 2) + i];
#pragma unroll
            for (int j = 0; j < 4; j++) b[j] = Bs[kk][(tx << 2) + j];
#pragma unroll
            for (int i = 0; i < 4; i++)
#pragma unroll
                for (int j = 0; j < 4; j++) acc[i][j] = fmaf(a[i], b[j], acc[i][j]);
        }
        __syncthreads();
    }
#pragma unroll
    for (int i = 0; i < 4; i++) {
        int row = m0 + (ty << 2) + i;
#pragma unroll
        for (int j = 0; j < 4; j++) {
            int col = n0 + (tx << 2) + j;
            float v = acc[i][j] + b1[e * DF + col];
            g_h[(size_t)row * DF + col] = fmaxf(v, 0.0f);
        }
    }
}

// ---------------- GEMM2: out += w * (h @ W2[e] + b2[e]) ----------------
__global__ __launch_bounds__(256) void gemm2_kernel(const float* __restrict__ W2,
                                                    const float* __restrict__ b2,
                                                    float* __restrict__ out) {
    __shared__ float As[BK][BM];
    __shared__ float Bs[BK][BN];
    const int n0 = blockIdx.x * BN;
    const int m0 = blockIdx.y * BM;
    const int e  = g_row_expert[m0];
    const float* __restrict__ W = W2 + (size_t)e * DF * DM;

    const int tid = threadIdx.x;
    const int am = tid >> 2, ak = (tid & 3) << 2;
    const int bk = tid >> 4, bn = (tid & 15) << 2;
    const int tx = tid & 15, ty = tid >> 4;

    const float* __restrict__ hrow = g_h + (size_t)(m0 + am) * DF;

    float acc[4][4];
#pragma unroll
    for (int i = 0; i < 4; i++)
#pragma unroll
        for (int j = 0; j < 4; j++) acc[i][j] = 0.0f;

    for (int k0 = 0; k0 < DF; k0 += BK) {
        float4 av = *(const float4*)(hrow + k0 + ak);
        As[ak + 0][am] = av.x; As[ak + 1][am] = av.y;
        As[ak + 2][am] = av.z; As[ak + 3][am] = av.w;
        *(float4*)&Bs[bk][bn] = *(const float4*)(W + (size_t)(k0 + bk) * DM + n0 + bn);
        __syncthreads();
#pragma unroll
        for (int kk = 0; kk < BK; kk++) {
            float a[4], b[4];
#pragma unroll
            for (int i = 0; i < 4; i++) a[i] = As[kk][(ty << 2) + i];
#pragma unroll
            for (int j = 0; j < 4; j++) b[j] = Bs[kk][(tx << 2) + j];
#pragma unroll
            for (int i = 0; i < 4; i++)
#pragma unroll
                for (int j = 0; j < 4; j++) acc[i][j] = fmaf(a[i], b[j], acc[i][j]);
        }
        __syncthreads();
    }
#pragma unroll
    for (int i = 0; i < 4; i++) {
        int row = m0 + (ty << 2) + i;
        int tok = g_row_token[row];
        if (tok < 0) continue;
        float w = g_row_w[row];
#pragma unroll
        for (int j = 0; j < 4; j++) {
            int col = n0 + (tx << 2) + j;
            float v = acc[i][j] + b2[e * DM + col];
            atomicAdd(&out[(size_t)tok * DM + col], w * v);
        }
    }
}

// ---------------- launch ----------------
extern "C" void kernel_launch(void* const* d_in, const int* in_sizes, int n_in,
                              void* d_out, int out_size) {
    const float* x  = (const float*)d_in[0];
    const float* Wg = (const float*)d_in[1];
    const float* W1 = (const float*)d_in[2];
    const float* b1 = (const float*)d_in[3];
    const float* W2 = (const float*)d_in[4];
    const float* b2 = (const float*)d_in[5];
    float* out = (float*)d_out;

    init_kernel<<<(out_size + 255) / 256, 256>>>(out, out_size);
    route_kernel<<<S, 128>>>(x, Wg);
    scan_kernel<<<1, 256>>>();
    fill_kernel<<<(S * TOPK + 255) / 256, 256>>>();
    gemm1_kernel<<<dim3(DF / BN, MTILES), 256>>>(x, W1, b1);
    gemm2_kernel<<<dim3(DM / BN, MTILES), 256>>>(W2, b2, out);
}

// round 7
// speedup vs baseline: 1.8031x; 1.8031x over previous
#include <cuda_runtime.h>
#include <cuda_bf16.h>
#include <cstdint>
#include <math.h>

#define S    4096
#define DM   768
#define DF   3072
#define NE   8
#define TOPK 2
#define BM   128
#define BN   64
#define BK   16
#define MTILES  72                    // 72*128 = 9216 >= 8192 + 8*127
#define MAXROWS (MTILES * BM)

// ---------------- device scratch ----------------
__device__ int   g_topi[TOPK * S];
__device__ float g_topw[TOPK * S];
__device__ int   g_counts[NE];
__device__ int   g_fill[NE];
__device__ int   g_padoff[NE + 1];
__device__ int   g_row_token[MAXROWS];
__device__ float g_row_w[MAXROWS];
__device__ int   g_tile_expert[MTILES];
__device__ __align__(16) float g_h[(size_t)MAXROWS * DF];   // ~113 MB fp32 scratch

// ---------------- helpers ----------------
__device__ __forceinline__ void mma16816(float* c, const uint32_t* a, const uint32_t* b) {
    asm volatile(
        "mma.sync.aligned.m16n8k16.row.col.f32.bf16.bf16.f32 "
        "{%0,%1,%2,%3}, {%4,%5,%6,%7}, {%8,%9}, {%0,%1,%2,%3};"
        : "+f"(c[0]), "+f"(c[1]), "+f"(c[2]), "+f"(c[3])
        : "r"(a[0]), "r"(a[1]), "r"(a[2]), "r"(a[3]), "r"(b[0]), "r"(b[1]));
}

// split (a,b) into bf16 hi pair (returned) and bf16 lo pair (out param).
// low 16 bits of each packed reg = first element (lower k index).
__device__ __forceinline__ uint32_t bsplit(float a, float b, uint32_t& lo) {
    __nv_bfloat16 ha = __float2bfloat16(a);
    __nv_bfloat16 hb = __float2bfloat16(b);
    __nv_bfloat16 la = __float2bfloat16(a - __bfloat162float(ha));
    __nv_bfloat16 lb = __float2bfloat16(b - __bfloat162float(hb));
    lo = (uint32_t)__bfloat16_as_ushort(la) | ((uint32_t)__bfloat16_as_ushort(lb) << 16);
    return (uint32_t)__bfloat16_as_ushort(ha) | ((uint32_t)__bfloat16_as_ushort(hb) << 16);
}

// ---------------- init ----------------
__global__ void init_kernel(float* __restrict__ out, int out_n) {
    int i = blockIdx.x * blockDim.x + threadIdx.x;
    if (i < out_n) out[i] = 0.0f;
    if (i < MAXROWS) { g_row_token[i] = -1; g_row_w[i] = 0.0f; }
    if (i < NE) { g_counts[i] = 0; g_fill[i] = 0; }
}

// ---------------- routing (verbatim from passing R1) ----------------
__global__ __launch_bounds__(128) void route_kernel(const float* __restrict__ x,
                                                    const float* __restrict__ Wg) {
    const int s = blockIdx.x;
    const float* __restrict__ xr = x + (size_t)s * DM;
    float acc[NE];
#pragma unroll
    for (int e = 0; e < NE; e++) acc[e] = 0.0f;
    for (int kk = threadIdx.x; kk < DM; kk += 128) {
        float xv = xr[kk];
#pragma unroll
        for (int e = 0; e < NE; e++) acc[e] = fmaf(xv, Wg[kk * NE + e], acc[e]);
    }
#pragma unroll
    for (int e = 0; e < NE; e++)
#pragma unroll
        for (int o = 16; o > 0; o >>= 1) acc[e] += __shfl_xor_sync(0xFFFFFFFFu, acc[e], o);
    __shared__ float sred[4][NE];
    int warp = threadIdx.x >> 5, lane = threadIdx.x & 31;
    if (lane == 0)
#pragma unroll
        for (int e = 0; e < NE; e++) sred[warp][e] = acc[e];
    __syncthreads();
    if (threadIdx.x == 0) {
        float l[NE];
#pragma unroll
        for (int e = 0; e < NE; e++) l[e] = sred[0][e] + sred[1][e] + sred[2][e] + sred[3][e];
        int i1 = 0;
#pragma unroll
        for (int e = 1; e < NE; e++) if (l[e] > l[i1]) i1 = e;
        int i2 = (i1 == 0) ? 1 : 0;
#pragma unroll
        for (int e = 0; e < NE; e++) if (e != i1 && l[e] > l[i2]) i2 = e;
        float d = __expf(l[i2] - l[i1]);
        float inv = 1.0f / (1.0f + d);
        g_topi[0 * S + s] = i1; g_topw[0 * S + s] = inv;
        g_topi[1 * S + s] = i2; g_topw[1 * S + s] = d * inv;
        atomicAdd(&g_counts[i1], 1);
        atomicAdd(&g_counts[i2], 1);
    }
}

// ---------------- scan ----------------
__global__ void scan_kernel() {
    __shared__ int off[NE + 1];
    if (threadIdx.x == 0) {
        int acc = 0;
        for (int e = 0; e < NE; e++) {
            off[e] = acc; g_padoff[e] = acc;
            acc += ((g_counts[e] + BM - 1) / BM) * BM;
        }
        off[NE] = acc; g_padoff[NE] = acc;
    }
    __syncthreads();
    for (int t = threadIdx.x; t < MTILES; t += blockDim.x) {
        int r = t * BM;
        int e = 0;
#pragma unroll
        for (int j = 1; j < NE; j++) if (r >= off[j]) e = j;
        g_tile_expert[t] = (r < off[NE]) ? e : 0;
    }
}

// ---------------- fill ----------------
__global__ void fill_kernel() {
    int i = blockIdx.x * blockDim.x + threadIdx.x;
    if (i >= S * TOPK) return;
    int e = g_topi[i];
    int pos = atomicAdd(&g_fill[e], 1);
    int row = g_padoff[e] + pos;
    g_row_token[row] = i & (S - 1);
    g_row_w[row] = g_topw[i];
}

// ---------------- GEMM1: h = relu(X_gather @ W1[e] + b1[e]) (fp32 out) ----------------
// A: gathered x rows (fp32, stride DM). B: W1[e] natural [k][n] (stride DF).
__global__ __launch_bounds__(256) void gemm1_kernel(const float* __restrict__ x,
                                                    const float* __restrict__ W1,
                                                    const float* __restrict__ b1) {
    __shared__ uint32_t Ah[128][12], Al[128][12];   // [m][k-pair], pad 12
    __shared__ uint32_t Bh[8][72],  Bl[8][72];      // [k-pair][n], pad 72

    const int tid = threadIdx.x, lane = tid & 31, wid = tid >> 5;
    const int n0 = blockIdx.x * BN, m0 = blockIdx.y * BM;
    const int e = g_tile_expert[blockIdx.y];
    const int g = lane >> 2, q = lane & 3;
    const int wm = (wid & 3) * 32, wn = (wid >> 2) * 32;

    // A fill mapping: row = tid>>1, 4 k-pairs starting at (tid&1)*4
    const int ar = tid >> 1, aj = (tid & 1) * 4;
    int tok = g_row_token[m0 + ar];
    const float* __restrict__ arow = (tok >= 0) ? (x + (size_t)tok * DM) : (const float*)0;
    // B fill mapping: pair-row = wid (0..7), 2 cols at lane*2
    const int pr = wid, bc = lane * 2;
    const float* __restrict__ Wb = W1 + (size_t)e * DM * DF;

    float acc[2][4][4];
#pragma unroll
    for (int a = 0; a < 2; a++)
#pragma unroll
        for (int b = 0; b < 4; b++)
#pragma unroll
            for (int c = 0; c < 4; c++) acc[a][b][c] = 0.0f;

    for (int k0 = 0; k0 < DM; k0 += BK) {
        __syncthreads();
        // ---- fill A (convert fp32 -> packed bf16 hi/lo pairs along k) ----
        {
            float f[8];
            if (arow) {
                float4 v0 = *(const float4*)(arow + k0 + aj * 2);
                float4 v1 = *(const float4*)(arow + k0 + aj * 2 + 4);
                f[0] = v0.x; f[1] = v0.y; f[2] = v0.z; f[3] = v0.w;
                f[4] = v1.x; f[5] = v1.y; f[6] = v1.z; f[7] = v1.w;
            } else {
#pragma unroll
                for (int p = 0; p < 8; p++) f[p] = 0.0f;
            }
#pragma unroll
            for (int p = 0; p < 4; p++) {
                uint32_t lo;
                uint32_t hi = bsplit(f[2 * p], f[2 * p + 1], lo);
                Ah[ar][aj + p] = hi; Al[ar][aj + p] = lo;
            }
        }
        // ---- fill B: pack (k=2pr, k=2pr+1) along k for 2 n-cols ----
        {
            const float* r0p = Wb + (size_t)(k0 + 2 * pr) * DF + n0 + bc;
            const float* r1p = r0p + DF;
#pragma unroll
            for (int cc = 0; cc < 2; cc++) {
                uint32_t lo;
                uint32_t hi = bsplit(r0p[cc], r1p[cc], lo);
                Bh[pr][bc + cc] = hi; Bl[pr][bc + cc] = lo;
            }
        }
        __syncthreads();
        // ---- fragments (documented m16n8k16 thread mapping) ----
        uint32_t ah[2][4], al_[2][4];
#pragma unroll
        for (int mt = 0; mt < 2; mt++) {
            int r = wm + mt * 16 + g;
            ah[mt][0] = Ah[r][q];      al_[mt][0] = Al[r][q];
            ah[mt][1] = Ah[r + 8][q];  al_[mt][1] = Al[r + 8][q];
            ah[mt][2] = Ah[r][q + 4];  al_[mt][2] = Al[r][q + 4];
            ah[mt][3] = Ah[r + 8][q + 4]; al_[mt][3] = Al[r + 8][q + 4];
        }
#pragma unroll
        for (int nt = 0; nt < 4; nt++) {
            int c = wn + nt * 8 + g;
            uint32_t bh[2] = { Bh[q][c], Bh[q + 4][c] };
            uint32_t bl[2] = { Bl[q][c], Bl[q + 4][c] };
#pragma unroll
            for (int mt = 0; mt < 2; mt++) {
                mma16816(acc[mt][nt], ah[mt], bh);
                mma16816(acc[mt][nt], ah[mt], bl);
                mma16816(acc[mt][nt], al_[mt], bh);
            }
        }
    }

    // ---- epilogue: relu(+b1) -> g_h fp32 ----
#pragma unroll
    for (int mt = 0; mt < 2; mt++) {
        int row0 = m0 + wm + mt * 16 + g, row1 = row0 + 8;
#pragma unroll
        for (int nt = 0; nt < 4; nt++) {
            int col = n0 + wn + nt * 8 + 2 * q;
            float bv0 = b1[e * DF + col], bv1 = b1[e * DF + col + 1];
            g_h[(size_t)row0 * DF + col]     = fmaxf(acc[mt][nt][0] + bv0, 0.0f);
            g_h[(size_t)row0 * DF + col + 1] = fmaxf(acc[mt][nt][1] + bv1, 0.0f);
            g_h[(size_t)row1 * DF + col]     = fmaxf(acc[mt][nt][2] + bv0, 0.0f);
            g_h[(size_t)row1 * DF + col + 1] = fmaxf(acc[mt][nt][3] + bv1, 0.0f);
        }
    }
}

// ---------------- GEMM2: out += w * (h @ W2[e] + b2[e]) ----------------
__global__ __launch_bounds__(256) void gemm2_kernel(const float* __restrict__ W2,
                                                    const float* __restrict__ b2,
                                                    float* __restrict__ out) {
    __shared__ uint32_t Ah[128][12], Al[128][12];
    __shared__ uint32_t Bh[8][72],  Bl[8][72];

    const int tid = threadIdx.x, lane = tid & 31, wid = tid >> 5;
    const int n0 = blockIdx.x * BN, m0 = blockIdx.y * BM;
    const int e = g_tile_expert[blockIdx.y];
    const int g = lane >> 2, q = lane & 3;
    const int wm = (wid & 3) * 32, wn = (wid >> 2) * 32;

    const int ar = tid >> 1, aj = (tid & 1) * 4;
    const float* __restrict__ arow = g_h + (size_t)(m0 + ar) * DF;
    const int pr = wid, bc = lane * 2;
    const float* __restrict__ Wb = W2 + (size_t)e * DF * DM;

    float acc[2][4][4];
#pragma unroll
    for (int a = 0; a < 2; a++)
#pragma unroll
        for (int b = 0; b < 4; b++)
#pragma unroll
            for (int c = 0; c < 4; c++) acc[a][b][c] = 0.0f;

    for (int k0 = 0; k0 < DF; k0 += BK) {
        __syncthreads();
        {
            float4 v0 = *(const float4*)(arow + k0 + aj * 2);
            float4 v1 = *(const float4*)(arow + k0 + aj * 2 + 4);
            float f[8] = { v0.x, v0.y, v0.z, v0.w, v1.x, v1.y, v1.z, v1.w };
#pragma unroll
            for (int p = 0; p < 4; p++) {
                uint32_t lo;
                uint32_t hi = bsplit(f[2 * p], f[2 * p + 1], lo);
                Ah[ar][aj + p] = hi; Al[ar][aj + p] = lo;
            }
        }
        {
            const float* r0p = Wb + (size_t)(k0 + 2 * pr) * DM + n0 + bc;
            const float* r1p = r0p + DM;
#pragma unroll
            for (int cc = 0; cc < 2; cc++) {
                uint32_t lo;
                uint32_t hi = bsplit(r0p[cc], r1p[cc], lo);
                Bh[pr][bc + cc] = hi; Bl[pr][bc + cc] = lo;
            }
        }
        __syncthreads();
        uint32_t ah[2][4], al_[2][4];
#pragma unroll
        for (int mt = 0; mt < 2; mt++) {
            int r = wm + mt * 16 + g;
            ah[mt][0] = Ah[r][q];      al_[mt][0] = Al[r][q];
            ah[mt][1] = Ah[r + 8][q];  al_[mt][1] = Al[r + 8][q];
            ah[mt][2] = Ah[r][q + 4];  al_[mt][2] = Al[r][q + 4];
            ah[mt][3] = Ah[r + 8][q + 4]; al_[mt][3] = Al[r + 8][q + 4];
        }
#pragma unroll
        for (int nt = 0; nt < 4; nt++) {
            int c = wn + nt * 8 + g;
            uint32_t bh[2] = { Bh[q][c], Bh[q + 4][c] };
            uint32_t bl[2] = { Bl[q][c], Bl[q + 4][c] };
#pragma unroll
            for (int mt = 0; mt < 2; mt++) {
                mma16816(acc[mt][nt], ah[mt], bh);
                mma16816(acc[mt][nt], ah[mt], bl);
                mma16816(acc[mt][nt], al_[mt], bh);
            }
        }
    }

    // ---- epilogue: weighted atomic combine (2 contributions/element) ----
#pragma unroll
    for (int mt = 0; mt < 2; mt++) {
        int row0 = m0 + wm + mt * 16 + g, row1 = row0 + 8;
        int tok0 = g_row_token[row0], tok1 = g_row_token[row1];
        float w0 = g_row_w[row0], w1 = g_row_w[row1];
#pragma unroll
        for (int nt = 0; nt < 4; nt++) {
            int col = n0 + wn + nt * 8 + 2 * q;
            float bv0 = b2[e * DM + col], bv1 = b2[e * DM + col + 1];
            if (tok0 >= 0) {
                atomicAdd(out + (size_t)tok0 * DM + col,     w0 * (acc[mt][nt][0] + bv0));
                atomicAdd(out + (size_t)tok0 * DM + col + 1, w0 * (acc[mt][nt][1] + bv1));
            }
            if (tok1 >= 0) {
                atomicAdd(out + (size_t)tok1 * DM + col,     w1 * (acc[mt][nt][2] + bv0));
                atomicAdd(out + (size_t)tok1 * DM + col + 1, w1 * (acc[mt][nt][3] + bv1));
            }
        }
    }
}

// ---------------- launch ----------------
extern "C" void kernel_launch(void* const* d_in, const int* in_sizes, int n_in,
                              void* d_out, int out_size) {
    const float* x  = (const float*)d_in[0];
    const float* Wg = (const float*)d_in[1];
    const float* W1 = (const float*)d_in[2];
    const float* b1 = (const float*)d_in[3];
    const float* W2 = (const float*)d_in[4];
    const float* b2 = (const float*)d_in[5];
    float* out = (float*)d_out;

    init_kernel<<<(out_size + 255) / 256, 256>>>(out, out_size);
    route_kernel<<<S, 128>>>(x, Wg);
    scan_kernel<<<1, 256>>>();
    fill_kernel<<<(S * TOPK + 255) / 256, 256>>>();
    gemm1_kernel<<<dim3(DF / BN, MTILES), 256>>>(x, W1, b1);
    gemm2_kernel<<<dim3(DM / BN, MTILES), 256>>>(W2, b2, out);
}

// round 11
// speedup vs baseline: 2.0886x; 1.1583x over previous
#include <cuda_runtime.h>
#include <cuda_bf16.h>
#include <cstdint>
#include <math.h>

#define S    4096
#define DM   768
#define DF   3072
#define NE   8
#define TOPK 2
#define BM   128
#define BN   128
#define BK   32
#define MTILES  72                    // 72*128 = 9216 >= 8192 + 8*127
#define MAXROWS (MTILES * BM)
#define KP2  (DF / 2)                 // 1536 pair-cols for packed h

// ---------------- device scratch (total ~113.7 MB — R7-proven budget) ----------------
__device__ int   g_topi[TOPK * S];
__device__ float g_topw[TOPK * S];
__device__ int   g_counts[NE];
__device__ int   g_fill[NE];
__device__ int   g_padoff[NE + 1];
__device__ int   g_row_token[MAXROWS];
__device__ float g_row_w[MAXROWS];
__device__ int   g_tile_expert[MTILES];
// h packed as bf16 pairs: uint32 = (bf16 k_even) | (bf16 k_odd << 16)
__device__ __align__(16) uint32_t g_hp_hi[(size_t)MAXROWS * KP2];   // 56.6 MB
__device__ __align__(16) uint32_t g_hp_lo[(size_t)MAXROWS * KP2];   // 56.6 MB

// ---------------- helpers ----------------
__device__ __forceinline__ void mma16816(float* c, const uint32_t* a, const uint32_t* b) {
    asm volatile(
        "mma.sync.aligned.m16n8k16.row.col.f32.bf16.bf16.f32 "
        "{%0,%1,%2,%3}, {%4,%5,%6,%7}, {%8,%9}, {%0,%1,%2,%3};"
        : "+f"(c[0]), "+f"(c[1]), "+f"(c[2]), "+f"(c[3])
        : "r"(a[0]), "r"(a[1]), "r"(a[2]), "r"(a[3]), "r"(b[0]), "r"(b[1]));
}
__device__ __forceinline__ uint32_t bsplit(float a, float b, uint32_t& lo) {
    __nv_bfloat16 ha = __float2bfloat16(a);
    __nv_bfloat16 hb = __float2bfloat16(b);
    __nv_bfloat16 la = __float2bfloat16(a - __bfloat162float(ha));
    __nv_bfloat16 lb = __float2bfloat16(b - __bfloat162float(hb));
    lo = (uint32_t)__bfloat16_as_ushort(la) | ((uint32_t)__bfloat16_as_ushort(lb) << 16);
    return (uint32_t)__bfloat16_as_ushort(ha) | ((uint32_t)__bfloat16_as_ushort(hb) << 16);
}

// ---------------- init ----------------
__global__ void init_kernel(float* __restrict__ out, int out_n) {
    int i = blockIdx.x * blockDim.x + threadIdx.x;
    if (i < out_n) out[i] = 0.0f;
    if (i < MAXROWS) { g_row_token[i] = -1; g_row_w[i] = 0.0f; }
    if (i < NE) { g_counts[i] = 0; g_fill[i] = 0; }
}

// ---------------- routing (proven) ----------------
__global__ __launch_bounds__(128) void route_kernel(const float* __restrict__ x,
                                                    const float* __restrict__ Wg) {
    const int s = blockIdx.x;
    const float* __restrict__ xr = x + (size_t)s * DM;
    float acc[NE];
#pragma unroll
    for (int e = 0; e < NE; e++) acc[e] = 0.0f;
    for (int kk = threadIdx.x; kk < DM; kk += 128) {
        float xv = xr[kk];
#pragma unroll
        for (int e = 0; e < NE; e++) acc[e] = fmaf(xv, Wg[kk * NE + e], acc[e]);
    }
#pragma unroll
    for (int e = 0; e < NE; e++)
#pragma unroll
        for (int o = 16; o > 0; o >>= 1) acc[e] += __shfl_xor_sync(0xFFFFFFFFu, acc[e], o);
    __shared__ float sred[4][NE];
    int warp = threadIdx.x >> 5, lane = threadIdx.x & 31;
    if (lane == 0)
#pragma unroll
        for (int e = 0; e < NE; e++) sred[warp][e] = acc[e];
    __syncthreads();
    if (threadIdx.x == 0) {
        float l[NE];
#pragma unroll
        for (int e = 0; e < NE; e++) l[e] = sred[0][e] + sred[1][e] + sred[2][e] + sred[3][e];
        int i1 = 0;
#pragma unroll
        for (int e = 1; e < NE; e++) if (l[e] > l[i1]) i1 = e;
        int i2 = (i1 == 0) ? 1 : 0;
#pragma unroll
        for (int e = 0; e < NE; e++) if (e != i1 && l[e] > l[i2]) i2 = e;
        float d = __expf(l[i2] - l[i1]);
        float inv = 1.0f / (1.0f + d);
        g_topi[0 * S + s] = i1; g_topw[0 * S + s] = inv;
        g_topi[1 * S + s] = i2; g_topw[1 * S + s] = d * inv;
        atomicAdd(&g_counts[i1], 1);
        atomicAdd(&g_counts[i2], 1);
    }
}

// ---------------- scan ----------------
__global__ void scan_kernel() {
    __shared__ int off[NE + 1];
    if (threadIdx.x == 0) {
        int acc = 0;
        for (int e = 0; e < NE; e++) {
            off[e] = acc; g_padoff[e] = acc;
            acc += ((g_counts[e] + BM - 1) / BM) * BM;
        }
        off[NE] = acc; g_padoff[NE] = acc;
    }
    __syncthreads();
    for (int t = threadIdx.x; t < MTILES; t += blockDim.x) {
        int r = t * BM;
        int e = 0;
#pragma unroll
        for (int j = 1; j < NE; j++) if (r >= off[j]) e = j;
        g_tile_expert[t] = (r < off[NE]) ? e : 0;
    }
}

// ---------------- fill ----------------
__global__ void fill_kernel() {
    int i = blockIdx.x * blockDim.x + threadIdx.x;
    if (i >= S * TOPK) return;
    int e = g_topi[i];
    int pos = atomicAdd(&g_fill[e], 1);
    int row = g_padoff[e] + pos;
    g_row_token[row] = i & (S - 1);
    g_row_w[row] = g_topw[i];
}

// ---------------- GEMM1: h = relu(X_gather @ W1[e] + b1[e]) -> packed hi/lo ----------------
// A: gathered x rows fp32 (stride DM); B: W1[e] natural [k][n] fp32 (stride DF).
__global__ __launch_bounds__(256) void gemm1_kernel(const float* __restrict__ x,
                                                    const float* __restrict__ W1,
                                                    const float* __restrict__ b1) {
    __shared__ uint32_t Ah[128][20], Al[128][20];    // [m][pair 0..15], pad 20
    __shared__ uint32_t Bh[16][136], Bl[16][136];    // [pair-row][n 0..127], pad 136

    const int tid = threadIdx.x, lane = tid & 31, wid = tid >> 5;
    const int n0 = blockIdx.x * BN, m0 = blockIdx.y * BM;
    const int e = g_tile_expert[blockIdx.y];
    const int g = lane >> 2, q = lane & 3;
    const int wm = (wid & 3) * 32, wn = (wid >> 2) * 64;

    const int ar = tid >> 1, aj = (tid & 1) * 8;     // A: row, pair base (8 pairs = 16 floats)
    const int br = tid >> 4, bc = (tid & 15) * 8;    // B: pair-row, col base (8 cols)
    const int tok = g_row_token[m0 + ar];
    const float* __restrict__ arow  = x + (size_t)(tok >= 0 ? tok : 0) * DM + 2 * aj;
    const float* __restrict__ brow0 = W1 + ((size_t)e * DM + 2 * br) * DF + n0 + bc;

    float acc[2][8][4];
#pragma unroll
    for (int a = 0; a < 2; a++)
#pragma unroll
        for (int b = 0; b < 8; b++)
#pragma unroll
            for (int c = 0; c < 4; c++) acc[a][b][c] = 0.0f;

    float4 a4[4], b40[2], b41[2];
#define G1_LOAD(k0) do {                                                       \
    if (tok >= 0) {                                                            \
        a4[0] = *(const float4*)(arow + (k0));                                 \
        a4[1] = *(const float4*)(arow + (k0) + 4);                             \
        a4[2] = *(const float4*)(arow + (k0) + 8);                             \
        a4[3] = *(const float4*)(arow + (k0) + 12);                            \
    } else {                                                                   \
        a4[0] = a4[1] = a4[2] = a4[3] = make_float4(0.f, 0.f, 0.f, 0.f);       \
    }                                                                          \
    b40[0] = *(const float4*)(brow0 + (size_t)(k0) * DF);                      \
    b40[1] = *(const float4*)(brow0 + (size_t)(k0) * DF + 4);                  \
    b41[0] = *(const float4*)(brow0 + (size_t)(k0) * DF + DF);                 \
    b41[1] = *(const float4*)(brow0 + (size_t)(k0) * DF + DF + 4);             \
} while (0)

    const int nk = DM / BK;   // 24
    G1_LOAD(0);
    for (int ks = 0; ks < nk; ks++) {
        __syncthreads();
        {   // convert + store A (16 floats -> 8 hi + 8 lo packed pairs)
            const float* fa = (const float*)a4;
            uint32_t th[8], tl[8];
#pragma unroll
            for (int p = 0; p < 8; p++) th[p] = bsplit(fa[2 * p], fa[2 * p + 1], tl[p]);
            *(uint4*)&Ah[ar][aj]     = *(uint4*)&th[0];
            *(uint4*)&Ah[ar][aj + 4] = *(uint4*)&th[4];
            *(uint4*)&Al[ar][aj]     = *(uint4*)&tl[0];
            *(uint4*)&Al[ar][aj + 4] = *(uint4*)&tl[4];
        }
        {   // convert + store B (pack k-pairs from two consecutive W rows)
            const float* f0 = (const float*)b40;
            const float* f1 = (const float*)b41;
            uint32_t th[8], tl[8];
#pragma unroll
            for (int c = 0; c < 8; c++) th[c] = bsplit(f0[c], f1[c], tl[c]);
            *(uint4*)&Bh[br][bc]     = *(uint4*)&th[0];
            *(uint4*)&Bh[br][bc + 4] = *(uint4*)&th[4];
            *(uint4*)&Bl[br][bc]     = *(uint4*)&tl[0];
            *(uint4*)&Bl[br][bc + 4] = *(uint4*)&tl[4];
        }
        __syncthreads();
        if (ks + 1 < nk) G1_LOAD((ks + 1) * BK);
#pragma unroll
        for (int sub = 0; sub < 2; sub++) {
            const int kb = sub * 8;
            uint32_t a_h[2][4], a_l[2][4];
#pragma unroll
            for (int mt = 0; mt < 2; mt++) {
                int r = wm + mt * 16 + g;
                a_h[mt][0] = Ah[r][kb + q];         a_l[mt][0] = Al[r][kb + q];
                a_h[mt][1] = Ah[r + 8][kb + q];     a_l[mt][1] = Al[r + 8][kb + q];
                a_h[mt][2] = Ah[r][kb + q + 4];     a_l[mt][2] = Al[r][kb + q + 4];
                a_h[mt][3] = Ah[r + 8][kb + q + 4]; a_l[mt][3] = Al[r + 8][kb + q + 4];
            }
#pragma unroll
            for (int nt = 0; nt < 8; nt++) {
                int c = wn + nt * 8 + g;
                uint32_t bh[2] = { Bh[kb + q][c], Bh[kb + q + 4][c] };
                uint32_t bl[2] = { Bl[kb + q][c], Bl[kb + q + 4][c] };
#pragma unroll
                for (int mt = 0; mt < 2; mt++) {
                    mma16816(acc[mt][nt], a_h[mt], bh);
                    mma16816(acc[mt][nt], a_h[mt], bl);
                    mma16816(acc[mt][nt], a_l[mt], bh);
                }
            }
        }
    }
#undef G1_LOAD

    // epilogue: relu(+b1) -> packed hi/lo pair planes (cols col, col+1)
#pragma unroll
    for (int mt = 0; mt < 2; mt++) {
        int row0 = m0 + wm + mt * 16 + g, row1 = row0 + 8;
#pragma unroll
        for (int nt = 0; nt < 8; nt++) {
            int col = n0 + wn + nt * 8 + 2 * q;
            float bv0 = b1[e * DF + col], bv1 = b1[e * DF + col + 1];
            float v00 = fmaxf(acc[mt][nt][0] + bv0, 0.0f);
            float v01 = fmaxf(acc[mt][nt][1] + bv1, 0.0f);
            float v10 = fmaxf(acc[mt][nt][2] + bv0, 0.0f);
            float v11 = fmaxf(acc[mt][nt][3] + bv1, 0.0f);
            uint32_t lo0, lo1;
            uint32_t hi0 = bsplit(v00, v01, lo0);
            uint32_t hi1 = bsplit(v10, v11, lo1);
            size_t o0 = (size_t)row0 * KP2 + (col >> 1);
            size_t o1 = (size_t)row1 * KP2 + (col >> 1);
            g_hp_hi[o0] = hi0; g_hp_lo[o0] = lo0;
            g_hp_hi[o1] = hi1; g_hp_lo[o1] = lo1;
        }
    }
}

// ---------------- GEMM2: out += w * (h @ W2[e] + b2[e]) ----------------
// A: packed h pair planes (pure copy); B: W2[e] natural [k][n] fp32 (stride DM).
__global__ __launch_bounds__(256) void gemm2_kernel(const float* __restrict__ W2,
                                                    const float* __restrict__ b2,
                                                    float* __restrict__ out) {
    __shared__ uint32_t Ah[128][20], Al[128][20];
    __shared__ uint32_t Bh[16][136], Bl[16][136];

    const int tid = threadIdx.x, lane = tid & 31, wid = tid >> 5;
    const int n0 = blockIdx.x * BN, m0 = blockIdx.y * BM;
    const int e = g_tile_expert[blockIdx.y];
    const int g = lane >> 2, q = lane & 3;
    const int wm = (wid & 3) * 32, wn = (wid >> 2) * 64;

    const int ar = tid >> 1, aj = (tid & 1) * 8;
    const int br = tid >> 4, bc = (tid & 15) * 8;
    const uint32_t* __restrict__ pAh = g_hp_hi + (size_t)(m0 + ar) * KP2 + aj;
    const uint32_t* __restrict__ pAl = g_hp_lo + (size_t)(m0 + ar) * KP2 + aj;
    const float* __restrict__ brow0 = W2 + ((size_t)e * DF + 2 * br) * DM + n0 + bc;

    float acc[2][8][4];
#pragma unroll
    for (int a = 0; a < 2; a++)
#pragma unroll
        for (int b = 0; b < 8; b++)
#pragma unroll
            for (int c = 0; c < 4; c++) acc[a][b][c] = 0.0f;

    uint4 rAh[2], rAl[2];
    float4 b40[2], b41[2];
#define G2_LOAD(ks_) do {                                                      \
    int kp0 = (ks_) * (BK / 2);                                                \
    rAh[0] = *(const uint4*)(pAh + kp0);                                       \
    rAh[1] = *(const uint4*)(pAh + kp0 + 4);                                   \
    rAl[0] = *(const uint4*)(pAl + kp0);                                       \
    rAl[1] = *(const uint4*)(pAl + kp0 + 4);                                   \
    int k0 = (ks_) * BK;                                                       \
    b40[0] = *(const float4*)(brow0 + (size_t)k0 * DM);                        \
    b40[1] = *(const float4*)(brow0 + (size_t)k0 * DM + 4);                    \
    b41[0] = *(const float4*)(brow0 + (size_t)k0 * DM + DM);                   \
    b41[1] = *(const float4*)(brow0 + (size_t)k0 * DM + DM + 4);               \
} while (0)

    const int nk = DF / BK;   // 96
    G2_LOAD(0);
    for (int ks = 0; ks < nk; ks++) {
        __syncthreads();
        *(uint4*)&Ah[ar][aj]     = rAh[0];
        *(uint4*)&Ah[ar][aj + 4] = rAh[1];
        *(uint4*)&Al[ar][aj]     = rAl[0];
        *(uint4*)&Al[ar][aj + 4] = rAl[1];
        {
            const float* f0 = (const float*)b40;
            const float* f1 = (const float*)b41;
            uint32_t th[8], tl[8];
#pragma unroll
            for (int c = 0; c < 8; c++) th[c] = bsplit(f0[c], f1[c], tl[c]);
            *(uint4*)&Bh[br][bc]     = *(uint4*)&th[0];
            *(uint4*)&Bh[br][bc + 4] = *(uint4*)&th[4];
            *(uint4*)&Bl[br][bc]     = *(uint4*)&tl[0];
            *(uint4*)&Bl[br][bc + 4] = *(uint4*)&tl[4];
        }
        __syncthreads();
        if (ks + 1 < nk) G2_LOAD(ks + 1);
#pragma unroll
        for (int sub = 0; sub < 2; sub++) {
            const int kb = sub * 8;
            uint32_t a_h[2][4], a_l[2][4];
#pragma unroll
            for (int mt = 0; mt < 2; mt++) {
                int r = wm + mt * 16 + g;
                a_h[mt][0] = Ah[r][kb + q];         a_l[mt][0] = Al[r][kb + q];
                a_h[mt][1] = Ah[r + 8][kb + q];     a_l[mt][1] = Al[r + 8][kb + q];
                a_h[mt][2] = Ah[r][kb + q + 4];     a_l[mt][2] = Al[r][kb + q + 4];
                a_h[mt][3] = Ah[r + 8][kb + q + 4]; a_l[mt][3] = Al[r + 8][kb + q + 4];
            }
#pragma unroll
            for (int nt = 0; nt < 8; nt++) {
                int c = wn + nt * 8 + g;
                uint32_t bh[2] = { Bh[kb + q][c], Bh[kb + q + 4][c] };
                uint32_t bl[2] = { Bl[kb + q][c], Bl[kb + q + 4][c] };
#pragma unroll
                for (int mt = 0; mt < 2; mt++) {
                    mma16816(acc[mt][nt], a_h[mt], bh);
                    mma16816(acc[mt][nt], a_h[mt], bl);
                    mma16816(acc[mt][nt], a_l[mt], bh);
                }
            }
        }
    }
#undef G2_LOAD

    // epilogue: weighted atomic combine (exactly 2 contributions/element)
#pragma unroll
    for (int mt = 0; mt < 2; mt++) {
        int row0 = m0 + wm + mt * 16 + g, row1 = row0 + 8;
        int tok0 = g_row_token[row0], tok1 = g_row_token[row1];
        float w0 = g_row_w[row0], w1 = g_row_w[row1];
#pragma unroll
        for (int nt = 0; nt < 8; nt++) {
            int col = n0 + wn + nt * 8 + 2 * q;
            float bv0 = b2[e * DM + col], bv1 = b2[e * DM + col + 1];
            if (tok0 >= 0) {
                atomicAdd(out + (size_t)tok0 * DM + col,     w0 * (acc[mt][nt][0] + bv0));
                atomicAdd(out + (size_t)tok0 * DM + col + 1, w0 * (acc[mt][nt][1] + bv1));
            }
            if (tok1 >= 0) {
                atomicAdd(out + (size_t)tok1 * DM + col,     w1 * (acc[mt][nt][2] + bv0));
                atomicAdd(out + (size_t)tok1 * DM + col + 1, w1 * (acc[mt][nt][3] + bv1));
            }
        }
    }
}

// ---------------- launch ----------------
extern "C" void kernel_launch(void* const* d_in, const int* in_sizes, int n_in,
                              void* d_out, int out_size) {
    const float* x  = (const float*)d_in[0];
    const float* Wg = (const float*)d_in[1];
    const float* W1 = (const float*)d_in[2];
    const float* b1 = (const float*)d_in[3];
    const float* W2 = (const float*)d_in[4];
    const float* b2 = (const float*)d_in[5];
    float* out = (float*)d_out;

    init_kernel<<<(out_size + 255) / 256, 256>>>(out, out_size);
    route_kernel<<<S, 128>>>(x, Wg);
    scan_kernel<<<1, 256>>>();
    fill_kernel<<<(S * TOPK + 255) / 256, 256>>>();
    gemm1_kernel<<<dim3(DF / BN, MTILES), 256>>>(x, W1, b1);
    gemm2_kernel<<<dim3(DM / BN, MTILES), 256>>>(W2, b2, out);
}

// round 13
// speedup vs baseline: 2.1111x; 1.0108x over previous
#include <cuda_runtime.h>
#include <cuda_bf16.h>
#include <cstdint>
#include <math.h>

#define S    4096
#define DM   768
#define DF   3072
#define NE   8
#define TOPK 2
#define BM   128
#define BN   128
#define BK   16
#define MTILES  72                    // 72*128 = 9216 >= 8192 + 8*127
#define MAXROWS (MTILES * BM)
#define KP2  (DF / 2)                 // 1536 pair-cols for packed h

// ---------------- device scratch (~113.7 MB — proven budget) ----------------
__device__ int   g_topi[TOPK * S];
__device__ float g_topw[TOPK * S];
__device__ int   g_counts[NE];
__device__ int   g_fill[NE];
__device__ int   g_padoff[NE + 1];
__device__ int   g_row_token[MAXROWS];
__device__ float g_row_w[MAXROWS];
__device__ int   g_tile_expert[MTILES];
__device__ __align__(16) uint32_t g_hp_hi[(size_t)MAXROWS * KP2];   // 56.6 MB
__device__ __align__(16) uint32_t g_hp_lo[(size_t)MAXROWS * KP2];   // 56.6 MB

// ---------------- helpers ----------------
__device__ __forceinline__ void mma16816(float* c, const uint32_t* a, const uint32_t* b) {
    asm volatile(
        "mma.sync.aligned.m16n8k16.row.col.f32.bf16.bf16.f32 "
        "{%0,%1,%2,%3}, {%4,%5,%6,%7}, {%8,%9}, {%0,%1,%2,%3};"
        : "+f"(c[0]), "+f"(c[1]), "+f"(c[2]), "+f"(c[3])
        : "r"(a[0]), "r"(a[1]), "r"(a[2]), "r"(a[3]), "r"(b[0]), "r"(b[1]));
}
__device__ __forceinline__ uint32_t bsplit(float a, float b, uint32_t& lo) {
    __nv_bfloat16 ha = __float2bfloat16(a);
    __nv_bfloat16 hb = __float2bfloat16(b);
    __nv_bfloat16 la = __float2bfloat16(a - __bfloat162float(ha));
    __nv_bfloat16 lb = __float2bfloat16(b - __bfloat162float(hb));
    lo = (uint32_t)__bfloat16_as_ushort(la) | ((uint32_t)__bfloat16_as_ushort(lb) << 16);
    return (uint32_t)__bfloat16_as_ushort(ha) | ((uint32_t)__bfloat16_as_ushort(hb) << 16);
}

// ---------------- init ----------------
__global__ void init_kernel(float* __restrict__ out, int out_n) {
    int i = blockIdx.x * blockDim.x + threadIdx.x;
    if (i < out_n) out[i] = 0.0f;
    if (i < MAXROWS) { g_row_token[i] = -1; g_row_w[i] = 0.0f; }
    if (i < NE) { g_counts[i] = 0; g_fill[i] = 0; }
}

// ---------------- routing (proven) ----------------
__global__ __launch_bounds__(128) void route_kernel(const float* __restrict__ x,
                                                    const float* __restrict__ Wg) {
    const int s = blockIdx.x;
    const float* __restrict__ xr = x + (size_t)s * DM;
    float acc[NE];
#pragma unroll
    for (int e = 0; e < NE; e++) acc[e] = 0.0f;
    for (int kk = threadIdx.x; kk < DM; kk += 128) {
        float xv = xr[kk];
#pragma unroll
        for (int e = 0; e < NE; e++) acc[e] = fmaf(xv, Wg[kk * NE + e], acc[e]);
    }
#pragma unroll
    for (int e = 0; e < NE; e++)
#pragma unroll
        for (int o = 16; o > 0; o >>= 1) acc[e] += __shfl_xor_sync(0xFFFFFFFFu, acc[e], o);
    __shared__ float sred[4][NE];
    int warp = threadIdx.x >> 5, lane = threadIdx.x & 31;
    if (lane == 0)
#pragma unroll
        for (int e = 0; e < NE; e++) sred[warp][e] = acc[e];
    __syncthreads();
    if (threadIdx.x == 0) {
        float l[NE];
#pragma unroll
        for (int e = 0; e < NE; e++) l[e] = sred[0][e] + sred[1][e] + sred[2][e] + sred[3][e];
        int i1 = 0;
#pragma unroll
        for (int e = 1; e < NE; e++) if (l[e] > l[i1]) i1 = e;
        int i2 = (i1 == 0) ? 1 : 0;
#pragma unroll
        for (int e = 0; e < NE; e++) if (e != i1 && l[e] > l[i2]) i2 = e;
        float d = __expf(l[i2] - l[i1]);
        float inv = 1.0f / (1.0f + d);
        g_topi[0 * S + s] = i1; g_topw[0 * S + s] = inv;
        g_topi[1 * S + s] = i2; g_topw[1 * S + s] = d * inv;
        atomicAdd(&g_counts[i1], 1);
        atomicAdd(&g_counts[i2], 1);
    }
}

// ---------------- scan ----------------
__global__ void scan_kernel() {
    __shared__ int off[NE + 1];
    if (threadIdx.x == 0) {
        int acc = 0;
        for (int e = 0; e < NE; e++) {
            off[e] = acc; g_padoff[e] = acc;
            acc += ((g_counts[e] + BM - 1) / BM) * BM;
        }
        off[NE] = acc; g_padoff[NE] = acc;
    }
    __syncthreads();
    for (int t = threadIdx.x; t < MTILES; t += blockDim.x) {
        int r = t * BM;
        int e = 0;
#pragma unroll
        for (int j = 1; j < NE; j++) if (r >= off[j]) e = j;
        g_tile_expert[t] = (r < off[NE]) ? e : 0;
    }
}

// ---------------- fill ----------------
__global__ void fill_kernel() {
    int i = blockIdx.x * blockDim.x + threadIdx.x;
    if (i >= S * TOPK) return;
    int e = g_topi[i];
    int pos = atomicAdd(&g_fill[e], 1);
    int row = g_padoff[e] + pos;
    g_row_token[row] = i & (S - 1);
    g_row_w[row] = g_topw[i];
}

// ---------------- GEMM1: h = relu(X_gather @ W1[e] + b1[e]) -> packed hi/lo ----------------
// A: gathered x rows fp32 (stride DM); B: W1[e] natural [k][n] fp32 (stride DF).
// Double-buffered smem, one __syncthreads per k-step.
__global__ __launch_bounds__(256) void gemm1_kernel(const float* __restrict__ x,
                                                    const float* __restrict__ W1,
                                                    const float* __restrict__ b1) {
    __shared__ uint32_t Ah[2][128][12], Al[2][128][12];   // [stage][m][pair 0..7], pad 12
    __shared__ uint32_t Bh[2][8][136],  Bl[2][8][136];    // [stage][pair-row][n], pad 136

    const int tid = threadIdx.x, lane = tid & 31, wid = tid >> 5;
    const int n0 = blockIdx.x * BN, m0 = blockIdx.y * BM;
    const int e = g_tile_expert[blockIdx.y];
    const int g = lane >> 2, q = lane & 3;
    const int wm = (wid & 3) * 32, wn = (wid >> 2) * 64;

    const int ar = tid >> 1, aj = (tid & 1) * 4;     // A: row, pair base (4 pairs = 8 floats)
    const int br = tid >> 5, bc = (tid & 31) * 4;    // B: pair-row, col base (4 cols)
    const int tok = g_row_token[m0 + ar];
    const float* __restrict__ arow  = x + (size_t)(tok >= 0 ? tok : 0) * DM + 2 * aj;
    const float* __restrict__ brow0 = W1 + ((size_t)e * DM + 2 * br) * DF + n0 + bc;

    float acc[2][8][4];
#pragma unroll
    for (int a = 0; a < 2; a++)
#pragma unroll
        for (int b = 0; b < 8; b++)
#pragma unroll
            for (int c = 0; c < 4; c++) acc[a][b][c] = 0.0f;

    float4 a40, a41, b40, b41;
#define G1_LOAD(ks_) do {                                                      \
    int k0 = (ks_) * BK;                                                       \
    if (tok >= 0) {                                                            \
        a40 = *(const float4*)(arow + k0);                                     \
        a41 = *(const float4*)(arow + k0 + 4);                                 \
    } else {                                                                   \
        a40 = a41 = make_float4(0.f, 0.f, 0.f, 0.f);                           \
    }                                                                          \
    b40 = *(const float4*)(brow0 + (size_t)k0 * DF);                           \
    b41 = *(const float4*)(brow0 + (size_t)k0 * DF + DF);                      \
} while (0)

#define G1_STORE(st) do {                                                      \
    float fa[8] = { a40.x, a40.y, a40.z, a40.w, a41.x, a41.y, a41.z, a41.w };  \
    uint32_t th[4], tl[4];                                                     \
    th[0] = bsplit(fa[0], fa[1], tl[0]);                                       \
    th[1] = bsplit(fa[2], fa[3], tl[1]);                                       \
    th[2] = bsplit(fa[4], fa[5], tl[2]);                                       \
    th[3] = bsplit(fa[6], fa[7], tl[3]);                                       \
    *(uint4*)&Ah[st][ar][aj] = *(uint4*)&th[0];                                \
    *(uint4*)&Al[st][ar][aj] = *(uint4*)&tl[0];                                \
    const float* f0 = (const float*)&b40;                                      \
    const float* f1 = (const float*)&b41;                                      \
    uint32_t uh[4], ul[4];                                                     \
    uh[0] = bsplit(f0[0], f1[0], ul[0]);                                       \
    uh[1] = bsplit(f0[1], f1[1], ul[1]);                                       \
    uh[2] = bsplit(f0[2], f1[2], ul[2]);                                       \
    uh[3] = bsplit(f0[3], f1[3], ul[3]);                                       \
    *(uint4*)&Bh[st][br][bc] = *(uint4*)&uh[0];                                \
    *(uint4*)&Bl[st][br][bc] = *(uint4*)&ul[0];                                \
} while (0)

    const int nk = DM / BK;   // 48
    G1_LOAD(0);
    G1_STORE(0);
    G1_LOAD(1);
    __syncthreads();
    for (int ks = 0; ks < nk; ks++) {
        const int st = ks & 1;
        if (ks + 1 < nk) G1_STORE((ks + 1) & 1);
        if (ks + 2 < nk) G1_LOAD(ks + 2);
        // ---- fragments + MMAs on stage st ----
        uint32_t a_h[2][4], a_l[2][4];
#pragma unroll
        for (int mt = 0; mt < 2; mt++) {
            int r = wm + mt * 16 + g;
            a_h[mt][0] = Ah[st][r][q];         a_l[mt][0] = Al[st][r][q];
            a_h[mt][1] = Ah[st][r + 8][q];     a_l[mt][1] = Al[st][r + 8][q];
            a_h[mt][2] = Ah[st][r][q + 4];     a_l[mt][2] = Al[st][r][q + 4];
            a_h[mt][3] = Ah[st][r + 8][q + 4]; a_l[mt][3] = Al[st][r + 8][q + 4];
        }
#pragma unroll
        for (int nt = 0; nt < 8; nt++) {
            int c = wn + nt * 8 + g;
            uint32_t bh[2] = { Bh[st][q][c], Bh[st][q + 4][c] };
            uint32_t bl[2] = { Bl[st][q][c], Bl[st][q + 4][c] };
#pragma unroll
            for (int mt = 0; mt < 2; mt++) {
                mma16816(acc[mt][nt], a_h[mt], bh);
                mma16816(acc[mt][nt], a_h[mt], bl);
                mma16816(acc[mt][nt], a_l[mt], bh);
            }
        }
        __syncthreads();
    }
#undef G1_LOAD
#undef G1_STORE

    // epilogue: relu(+b1) -> packed hi/lo pair planes
#pragma unroll
    for (int mt = 0; mt < 2; mt++) {
        int row0 = m0 + wm + mt * 16 + g, row1 = row0 + 8;
#pragma unroll
        for (int nt = 0; nt < 8; nt++) {
            int col = n0 + wn + nt * 8 + 2 * q;
            float bv0 = b1[e * DF + col], bv1 = b1[e * DF + col + 1];
            float v00 = fmaxf(acc[mt][nt][0] + bv0, 0.0f);
            float v01 = fmaxf(acc[mt][nt][1] + bv1, 0.0f);
            float v10 = fmaxf(acc[mt][nt][2] + bv0, 0.0f);
            float v11 = fmaxf(acc[mt][nt][3] + bv1, 0.0f);
            uint32_t lo0, lo1;
            uint32_t hi0 = bsplit(v00, v01, lo0);
            uint32_t hi1 = bsplit(v10, v11, lo1);
            size_t o0 = (size_t)row0 * KP2 + (col >> 1);
            size_t o1 = (size_t)row1 * KP2 + (col >> 1);
            g_hp_hi[o0] = hi0; g_hp_lo[o0] = lo0;
            g_hp_hi[o1] = hi1; g_hp_lo[o1] = lo1;
        }
    }
}

// ---------------- GEMM2: out += w * (h @ W2[e] + b2[e]) ----------------
__global__ __launch_bounds__(256) void gemm2_kernel(const float* __restrict__ W2,
                                                    const float* __restrict__ b2,
                                                    float* __restrict__ out) {
    __shared__ uint32_t Ah[2][128][12], Al[2][128][12];
    __shared__ uint32_t Bh[2][8][136],  Bl[2][8][136];

    const int tid = threadIdx.x, lane = tid & 31, wid = tid >> 5;
    const int n0 = blockIdx.x * BN, m0 = blockIdx.y * BM;
    const int e = g_tile_expert[blockIdx.y];
    const int g = lane >> 2, q = lane & 3;
    const int wm = (wid & 3) * 32, wn = (wid >> 2) * 64;

    const int ar = tid >> 1, aj = (tid & 1) * 4;
    const int br = tid >> 5, bc = (tid & 31) * 4;
    const uint32_t* __restrict__ pAh = g_hp_hi + (size_t)(m0 + ar) * KP2 + aj;
    const uint32_t* __restrict__ pAl = g_hp_lo + (size_t)(m0 + ar) * KP2 + aj;
    const float* __restrict__ brow0 = W2 + ((size_t)e * DF + 2 * br) * DM + n0 + bc;

    float acc[2][8][4];
#pragma unroll
    for (int a = 0; a < 2; a++)
#pragma unroll
        for (int b = 0; b < 8; b++)
#pragma unroll
            for (int c = 0; c < 4; c++) acc[a][b][c] = 0.0f;

    uint4 rAh, rAl;
    float4 b40, b41;
#define G2_LOAD(ks_) do {                                                      \
    int kp0 = (ks_) * (BK / 2);                                                \
    rAh = *(const uint4*)(pAh + kp0);                                          \
    rAl = *(const uint4*)(pAl + kp0);                                          \
    int k0 = (ks_) * BK;                                                       \
    b40 = *(const float4*)(brow0 + (size_t)k0 * DM);                           \
    b41 = *(const float4*)(brow0 + (size_t)k0 * DM + DM);                      \
} while (0)

#define G2_STORE(st) do {                                                      \
    *(uint4*)&Ah[st][ar][aj] = rAh;                                            \
    *(uint4*)&Al[st][ar][aj] = rAl;                                            \
    const float* f0 = (const float*)&b40;                                      \
    const float* f1 = (const float*)&b41;                                      \
    uint32_t uh[4], ul[4];                                                     \
    uh[0] = bsplit(f0[0], f1[0], ul[0]);                                       \
    uh[1] = bsplit(f0[1], f1[1], ul[1]);                                       \
    uh[2] = bsplit(f0[2], f1[2], ul[2]);                                       \
    uh[3] = bsplit(f0[3], f1[3], ul[3]);                                       \
    *(uint4*)&Bh[st][br][bc] = *(uint4*)&uh[0];                                \
    *(uint4*)&Bl[st][br][bc] = *(uint4*)&ul[0];                                \
} while (0)

    const int nk = DF / BK;   // 192
    G2_LOAD(0);
    G2_STORE(0);
    G2_LOAD(1);
    __syncthreads();
    for (int ks = 0; ks < nk; ks++) {
        const int st = ks & 1;
        if (ks + 1 < nk) G2_STORE((ks + 1) & 1);
        if (ks + 2 < nk) G2_LOAD(ks + 2);
        uint32_t a_h[2][4], a_l[2][4];
#pragma unroll
        for (int mt = 0; mt < 2; mt++) {
            int r = wm + mt * 16 + g;
            a_h[mt][0] = Ah[st][r][q];         a_l[mt][0] = Al[st][r][q];
            a_h[mt][1] = Ah[st][r + 8][q];     a_l[mt][1] = Al[st][r + 8][q];
            a_h[mt][2] = Ah[st][r][q + 4];     a_l[mt][2] = Al[st][r][q + 4];
            a_h[mt][3] = Ah[st][r + 8][q + 4]; a_l[mt][3] = Al[st][r + 8][q + 4];
        }
#pragma unroll
        for (int nt = 0; nt < 8; nt++) {
            int c = wn + nt * 8 + g;
            uint32_t bh[2] = { Bh[st][q][c], Bh[st][q + 4][c] };
            uint32_t bl[2] = { Bl[st][q][c], Bl[st][q + 4][c] };
#pragma unroll
            for (int mt = 0; mt < 2; mt++) {
                mma16816(acc[mt][nt], a_h[mt], bh);
                mma16816(acc[mt][nt], a_h[mt], bl);
                mma16816(acc[mt][nt], a_l[mt], bh);
            }
        }
        __syncthreads();
    }
#undef G2_LOAD
#undef G2_STORE

    // epilogue: weighted atomic combine (exactly 2 contributions/element)
#pragma unroll
    for (int mt = 0; mt < 2; mt++) {
        int row0 = m0 + wm + mt * 16 + g, row1 = row0 + 8;
        int tok0 = g_row_token[row0], tok1 = g_row_token[row1];
        float w0 = g_row_w[row0], w1 = g_row_w[row1];
#pragma unroll
        for (int nt = 0; nt < 8; nt++) {
            int col = n0 + wn + nt * 8 + 2 * q;
            float bv0 = b2[e * DM + col], bv1 = b2[e * DM + col + 1];
            if (tok0 >= 0) {
                atomicAdd(out + (size_t)tok0 * DM + col,     w0 * (acc[mt][nt][0] + bv0));
                atomicAdd(out + (size_t)tok0 * DM + col + 1, w0 * (acc[mt][nt][1] + bv1));
            }
            if (tok1 >= 0) {
                atomicAdd(out + (size_t)tok1 * DM + col,     w1 * (acc[mt][nt][2] + bv0));
                atomicAdd(out + (size_t)tok1 * DM + col + 1, w1 * (acc[mt][nt][3] + bv1));
            }
        }
    }
}

// ---------------- launch ----------------
extern "C" void kernel_launch(void* const* d_in, const int* in_sizes, int n_in,
                              void* d_out, int out_size) {
    const float* x  = (const float*)d_in[0];
    const float* Wg = (const float*)d_in[1];
    const float* W1 = (const float*)d_in[2];
    const float* b1 = (const float*)d_in[3];
    const float* W2 = (const float*)d_in[4];
    const float* b2 = (const float*)d_in[5];
    float* out = (float*)d_out;

    init_kernel<<<(out_size + 255) / 256, 256>>>(out, out_size);
    route_kernel<<<S, 128>>>(x, Wg);
    scan_kernel<<<1, 256>>>();
    fill_kernel<<<(S * TOPK + 255) / 256, 256>>>();
    gemm1_kernel<<<dim3(DF / BN, MTILES), 256>>>(x, W1, b1);
    gemm2_kernel<<<dim3(DM / BN, MTILES), 256>>>(W2, b2, out);
}